// round 1
// baseline (speedup 1.0000x reference)
#include <cuda_runtime.h>
#include <math.h>

// Problem constants
#define NM 100000
#define NS 20000
#define NT 200000
#define CC 64
#define EMT 1000000
#define EST 500000

// ---------------- static device scratch (no allocations allowed) ----------------
__device__ float g_h0[NM * CC];    // projected member features
__device__ float g_h1[NS * CC];    // projected skill features
__device__ float g_h2[NT * CC];    // projected team features
__device__ float g_o0[NM * CC];    // member aggregation (edge type 1)
__device__ float g_o1[NS * CC];    // skill aggregation (edge type 3)
__device__ float g_oT0[NT * CC];   // team aggregation (edge type 0)
__device__ float g_oT1[NT * CC];   // team aggregation (edge type 2)
__device__ float g_x2[NT * CC];    // combined team output -> next layer input
__device__ float g_as[4][NT * 2];  // per-edge-type source attention terms
__device__ float g_ad[4][NT * 2];  // per-edge-type dest attention terms
__device__ float g_mx[4][NT * 2];  // segment max
__device__ float g_sm[4][NT * 2];  // segment sum of exp
__device__ float g_lg[4][EMT * 2]; // per-edge logits -> exp values
__device__ float g_acc[2 * CC];    // semantic attention accumulators (team, K=2)
__device__ float g_w[2];           // semantic softmax weights

// ---------------- helpers ----------------
__device__ __forceinline__ void atomicMaxF(float* addr, float v) {
    if (v >= 0.0f) atomicMax((int*)addr, __float_as_int(v));
    else           atomicMin((unsigned int*)addr, __float_as_uint(v));
}

// ---------------- fused projection + attention-dot kernel ----------------
// h = x @ W + b   (per node row), plus up to 4 fused attention dot products:
//   ao[v][n*2+h] = sum_d h[n, h*32+d] * av[v][h*32+d]
__global__ __launch_bounds__(256) void proj_att_kernel(
    const float* __restrict__ x, const float* __restrict__ W,
    const float* __restrict__ bias, float* __restrict__ hout, int N,
    const float* av0, float* ao0, const float* av1, float* ao1,
    const float* av2, float* ao2, const float* av3, float* ao3)
{
    __shared__ float sWt[64 * 68];   // transposed weights: sWt[c*68 + k]
    __shared__ float sAv[4 * 64];
    __shared__ float sX[8][512];     // 8 warps x 8 rows x 64

    const float* avs[4] = {av0, av1, av2, av3};
    float*       aos[4] = {ao0, ao1, ao2, ao3};

    int t = threadIdx.x;
    for (int i = t; i < 4096; i += 256) { int k = i >> 6, c = i & 63; sWt[c * 68 + k] = W[i]; }
    if (t < 64) {
        #pragma unroll
        for (int v = 0; v < 4; v++) if (avs[v]) sAv[v * 64 + t] = avs[v][t];
    }
    __syncthreads();

    int lane = t & 31, slot = t >> 5;
    long r0 = (long)blockIdx.x * 64 + slot * 8;

    // load 8 rows of x into shared (zero padded)
    for (int j = lane; j < 128; j += 32) {
        int r = j >> 4, kk = (j & 15) * 4;
        float4 vv = make_float4(0.f, 0.f, 0.f, 0.f);
        if (r0 + r < N) vv = *(const float4*)(x + (r0 + r) * 64 + kk);
        *(float4*)&sX[slot][r * 64 + kk] = vv;
    }
    __syncwarp();

    float b0 = bias[lane], b1 = bias[lane + 32];
    float acc0[8], acc1[8];
    #pragma unroll
    for (int r = 0; r < 8; r++) { acc0[r] = b0; acc1[r] = b1; }

    #pragma unroll
    for (int k = 0; k < 64; k += 4) {
        float4 w0 = *(const float4*)&sWt[lane * 68 + k];
        float4 w1 = *(const float4*)&sWt[(lane + 32) * 68 + k];
        #pragma unroll
        for (int r = 0; r < 8; r++) {
            float4 xv = *(const float4*)&sX[slot][r * 64 + k];
            acc0[r] += xv.x * w0.x + xv.y * w0.y + xv.z * w0.z + xv.w * w0.w;
            acc1[r] += xv.x * w1.x + xv.y * w1.y + xv.z * w1.z + xv.w * w1.w;
        }
    }

    #pragma unroll
    for (int r = 0; r < 8; r++) {
        if (r0 + r < N) {
            hout[(r0 + r) * 64 + lane]      = acc0[r];
            hout[(r0 + r) * 64 + lane + 32] = acc1[r];
        }
    }

    // fused attention dots
    for (int v = 0; v < 4; v++) {
        if (!aos[v]) continue;
        float a0v = sAv[v * 64 + lane], a1v = sAv[v * 64 + lane + 32];
        #pragma unroll
        for (int r = 0; r < 8; r++) {
            float p0 = acc0[r] * a0v;
            float p1 = acc1[r] * a1v;
            #pragma unroll
            for (int off = 16; off; off >>= 1) {
                p0 += __shfl_xor_sync(0xffffffffu, p0, off);
                p1 += __shfl_xor_sync(0xffffffffu, p1, off);
            }
            if (lane == 0 && r0 + r < N) {
                aos[v][(r0 + r) * 2]     = p0;
                aos[v][(r0 + r) * 2 + 1] = p1;
            }
        }
    }
}

// ---------------- semantic attention reduction: acc[c] += sum_n tanh((o@kW+kb)[n,c]) ----------------
__global__ __launch_bounds__(256) void sem_reduce_kernel(
    const float* __restrict__ o, const float* __restrict__ W,
    const float* __restrict__ bias, float* __restrict__ acc, int N)
{
    __shared__ float sWt[64 * 68];
    __shared__ float sX[8][512];
    __shared__ float sAcc[64];

    int t = threadIdx.x;
    for (int i = t; i < 4096; i += 256) { int k = i >> 6, c = i & 63; sWt[c * 68 + k] = W[i]; }
    if (t < 64) sAcc[t] = 0.f;
    __syncthreads();

    int lane = t & 31, slot = t >> 5;
    long r0 = (long)blockIdx.x * 64 + slot * 8;

    for (int j = lane; j < 128; j += 32) {
        int r = j >> 4, kk = (j & 15) * 4;
        float4 vv = make_float4(0.f, 0.f, 0.f, 0.f);
        if (r0 + r < N) vv = *(const float4*)(o + (r0 + r) * 64 + kk);
        *(float4*)&sX[slot][r * 64 + kk] = vv;
    }
    __syncwarp();

    float b0 = bias[lane], b1 = bias[lane + 32];
    float acc0[8], acc1[8];
    #pragma unroll
    for (int r = 0; r < 8; r++) { acc0[r] = b0; acc1[r] = b1; }

    #pragma unroll
    for (int k = 0; k < 64; k += 4) {
        float4 w0 = *(const float4*)&sWt[lane * 68 + k];
        float4 w1 = *(const float4*)&sWt[(lane + 32) * 68 + k];
        #pragma unroll
        for (int r = 0; r < 8; r++) {
            float4 xv = *(const float4*)&sX[slot][r * 64 + k];
            acc0[r] += xv.x * w0.x + xv.y * w0.y + xv.z * w0.z + xv.w * w0.w;
            acc1[r] += xv.x * w1.x + xv.y * w1.y + xv.z * w1.z + xv.w * w1.w;
        }
    }

    float s0 = 0.f, s1 = 0.f;
    #pragma unroll
    for (int r = 0; r < 8; r++) {
        if (r0 + r < N) { s0 += tanhf(acc0[r]); s1 += tanhf(acc1[r]); }
    }
    atomicAdd(&sAcc[lane], s0);
    atomicAdd(&sAcc[lane + 32], s1);
    __syncthreads();
    if (t < 64) atomicAdd(&acc[t], sAcc[t]);
}

// ---------------- edge passes ----------------
__global__ void fill_kernel(float* p, float v, int n) {
    int i = blockIdx.x * blockDim.x + threadIdx.x;
    if (i < n) p[i] = v;
}

__global__ void edge_logit_max_kernel(const int* __restrict__ src, const int* __restrict__ dst,
                                      const float* __restrict__ as, const float* __restrict__ ad,
                                      float* __restrict__ lg, float* __restrict__ mx, int E)
{
    int e = blockIdx.x * blockDim.x + threadIdx.x;
    if (e >= E) return;
    int s = src[e], d = dst[e];
    #pragma unroll
    for (int h = 0; h < 2; h++) {
        float v = as[s * 2 + h] + ad[d * 2 + h];
        v = (v >= 0.f) ? v : 0.2f * v;   // leaky_relu 0.2
        lg[e * 2 + h] = v;
        atomicMaxF(&mx[d * 2 + h], v);
    }
}

__global__ void edge_expsum_kernel(const int* __restrict__ dst, float* __restrict__ lg,
                                   const float* __restrict__ mx, float* __restrict__ sm, int E)
{
    int e = blockIdx.x * blockDim.x + threadIdx.x;
    if (e >= E) return;
    int d = dst[e];
    #pragma unroll
    for (int h = 0; h < 2; h++) {
        float ex = __expf(lg[e * 2 + h] - mx[d * 2 + h]);
        lg[e * 2 + h] = ex;
        atomicAdd(&sm[d * 2 + h], ex);
    }
}

// warp per edge: agg[dst] += e * h[src]
__global__ void edge_agg_kernel(const int* __restrict__ src, const int* __restrict__ dst,
                                const float* __restrict__ hsrc, const float* __restrict__ lg,
                                float* __restrict__ agg, int E)
{
    int warp = (int)(((long)blockIdx.x * blockDim.x + threadIdx.x) >> 5);
    int lane = threadIdx.x & 31;
    if (warp >= E) return;
    int s = src[warp], d = dst[warp];
    int head = lane >> 4;
    float ex = lg[warp * 2 + head];
    float2 hv = ((const float2*)(hsrc + (long)s * 64))[lane];
    float* o = agg + (long)d * 64 + lane * 2;
    atomicAdd(o,     hv.x * ex);
    atomicAdd(o + 1, hv.y * ex);
}

// agg[n,c] = relu(agg[n,c] / (sum[n, head(c)] + 1e-16))
__global__ void norm_relu_kernel(float* __restrict__ agg, const float* __restrict__ sm, int N)
{
    long i = (long)blockIdx.x * blockDim.x + threadIdx.x;
    if (i >= (long)N * 32) return;
    int n = (int)(i >> 5), lane = (int)(i & 31), head = lane >> 4;
    float s = sm[n * 2 + head] + 1e-16f;
    float2 v = ((float2*)agg)[i];
    v.x /= s; v.y /= s;
    v.x = v.x > 0.f ? v.x : 0.f;
    v.y = v.y > 0.f ? v.y : 0.f;
    ((float2*)agg)[i] = v;
}

// ---------------- semantic finalize + combine ----------------
__global__ void sem_finalize_kernel(const float* __restrict__ acc, const float* __restrict__ q,
                                    float* __restrict__ wout)
{
    __shared__ float s0[64], s1[64];
    int t = threadIdx.x;
    s0[t] = q[t] * acc[t]      * (1.0f / NT);
    s1[t] = q[t] * acc[64 + t] * (1.0f / NT);
    __syncthreads();
    if (t == 0) {
        float a = 0.f, b = 0.f;
        for (int i = 0; i < 64; i++) { a += s0[i]; b += s1[i]; }
        float m = fmaxf(a, b);
        float e0 = __expf(a - m), e1 = __expf(b - m);
        float inv = 1.0f / (e0 + e1);
        wout[0] = e0 * inv;
        wout[1] = e1 * inv;
    }
}

__global__ void combine_kernel(float* __restrict__ xo, const float* __restrict__ a,
                               const float* __restrict__ b, const float* __restrict__ w)
{
    long i = (long)blockIdx.x * blockDim.x + threadIdx.x;
    if (i >= (long)NT * 16) return;
    float w0 = w[0], w1 = w[1];
    float4 va = ((const float4*)a)[i];
    float4 vb = ((const float4*)b)[i];
    float4 r;
    r.x = w0 * va.x + w1 * vb.x;
    r.y = w0 * va.y + w1 * vb.y;
    r.z = w0 * va.z + w1 * vb.z;
    r.w = w0 * va.w + w1 * vb.w;
    ((float4*)xo)[i] = r;
}

// ---------------- host orchestration ----------------
extern "C" void kernel_launch(void* const* d_in, const int* in_sizes, int n_in,
                              void* d_out, int out_size)
{
    (void)in_sizes; (void)n_in; (void)out_size;
    const float* x_m  = (const float*)d_in[0];
    const float* x_s  = (const float*)d_in[1];
    const float* x_t  = (const float*)d_in[2];
    const int* esrc[4] = {(const int*)d_in[3], (const int*)d_in[5], (const int*)d_in[7], (const int*)d_in[9]};
    const int* edst[4] = {(const int*)d_in[4], (const int*)d_in[6], (const int*)d_in[8], (const int*)d_in[10]};
    const float* Wp   = (const float*)d_in[11];
    const float* bp   = (const float*)d_in[12];
    const float* aS   = (const float*)d_in[13];
    const float* aD   = (const float*)d_in[14];
    const float* kWp  = (const float*)d_in[15];
    const float* kbp  = (const float*)d_in[16];
    const float* qp   = (const float*)d_in[17];
    const float* linW = (const float*)d_in[18];
    const float* linb = (const float*)d_in[19];
    float* out = (float*)d_out;

    float *h0, *h1, *h2, *o0, *o1, *oT0, *oT1, *x2, *acc, *wsem;
    float *asb, *adb, *mxb, *smb, *lgb;
    cudaGetSymbolAddress((void**)&h0,  g_h0);
    cudaGetSymbolAddress((void**)&h1,  g_h1);
    cudaGetSymbolAddress((void**)&h2,  g_h2);
    cudaGetSymbolAddress((void**)&o0,  g_o0);
    cudaGetSymbolAddress((void**)&o1,  g_o1);
    cudaGetSymbolAddress((void**)&oT0, g_oT0);
    cudaGetSymbolAddress((void**)&oT1, g_oT1);
    cudaGetSymbolAddress((void**)&x2,  g_x2);
    cudaGetSymbolAddress((void**)&acc, g_acc);
    cudaGetSymbolAddress((void**)&wsem, g_w);
    cudaGetSymbolAddress((void**)&asb, g_as);
    cudaGetSymbolAddress((void**)&adb, g_ad);
    cudaGetSymbolAddress((void**)&mxb, g_mx);
    cudaGetSymbolAddress((void**)&smb, g_sm);
    cudaGetSymbolAddress((void**)&lgb, g_lg);

    float* as_[4]; float* ad_[4]; float* mx_[4]; float* sm_[4]; float* lg_[4];
    for (int e = 0; e < 4; e++) {
        as_[e] = asb + (long)e * NT * 2;
        ad_[e] = adb + (long)e * NT * 2;
        mx_[e] = mxb + (long)e * NT * 2;
        sm_[e] = smb + (long)e * NT * 2;
        lg_[e] = lgb + (long)e * EMT * 2;
    }

    const int EN[4] = {EMT, EMT, EST, EST};
    const int ND[4] = {NT, NM, NT, NS};   // destination node counts
    float* AGG[4] = {oT0, o0, oT1, o1};

    for (int l = 0; l < 3; l++) {
        const float* xm = l ? o0 : x_m;
        const float* xs = l ? o1 : x_s;
        const float* xt = l ? x2 : x_t;
        const float* W0 = Wp + (long)(l * 3 + 0) * 4096;
        const float* W1 = Wp + (long)(l * 3 + 1) * 4096;
        const float* W2 = Wp + (long)(l * 3 + 2) * 4096;
        const float* b0 = bp + (long)(l * 3 + 0) * 64;
        const float* b1 = bp + (long)(l * 3 + 1) * 64;
        const float* b2 = bp + (long)(l * 3 + 2) * 64;

        // projections with fused attention dot products
        proj_att_kernel<<<(NM + 63) / 64, 256>>>(xm, W0, b0, h0, NM,
            aS + (long)(l * 4 + 0) * 64, as_[0],
            aD + (long)(l * 4 + 1) * 64, ad_[1],
            nullptr, nullptr, nullptr, nullptr);
        proj_att_kernel<<<(NS + 63) / 64, 256>>>(xs, W1, b1, h1, NS,
            aS + (long)(l * 4 + 2) * 64, as_[2],
            aD + (long)(l * 4 + 3) * 64, ad_[3],
            nullptr, nullptr, nullptr, nullptr);
        proj_att_kernel<<<(NT + 63) / 64, 256>>>(xt, W2, b2, h2, NT,
            aS + (long)(l * 4 + 1) * 64, as_[1],
            aS + (long)(l * 4 + 3) * 64, as_[3],
            aD + (long)(l * 4 + 0) * 64, ad_[0],
            aD + (long)(l * 4 + 2) * 64, ad_[2]);

        // init per-edge-type buffers
        for (int e = 0; e < 4; e++) {
            fill_kernel<<<(ND[e] * 2 + 255) / 256, 256>>>(mx_[e], -INFINITY, ND[e] * 2);
            cudaMemsetAsync(sm_[e], 0, (size_t)ND[e] * 2 * sizeof(float));
        }
        cudaMemsetAsync(o0,  0, (size_t)NM * CC * sizeof(float));
        cudaMemsetAsync(o1,  0, (size_t)NS * CC * sizeof(float));
        cudaMemsetAsync(oT0, 0, (size_t)NT * CC * sizeof(float));
        cudaMemsetAsync(oT1, 0, (size_t)NT * CC * sizeof(float));

        const float* HS[4] = {h0, h2, h1, h2};
        for (int e = 0; e < 4; e++) {
            int E = EN[e];
            edge_logit_max_kernel<<<(E + 255) / 256, 256>>>(esrc[e], edst[e], as_[e], ad_[e], lg_[e], mx_[e], E);
            edge_expsum_kernel<<<(E + 255) / 256, 256>>>(edst[e], lg_[e], mx_[e], sm_[e], E);
            long thr = (long)E * 32;
            edge_agg_kernel<<<(unsigned)((thr + 255) / 256), 256>>>(esrc[e], edst[e], HS[e], lg_[e], AGG[e], E);
        }

        norm_relu_kernel<<<(unsigned)(((long)NT * 32 + 255) / 256), 256>>>(oT0, sm_[0], NT);
        norm_relu_kernel<<<(unsigned)(((long)NM * 32 + 255) / 256), 256>>>(o0,  sm_[1], NM);
        norm_relu_kernel<<<(unsigned)(((long)NT * 32 + 255) / 256), 256>>>(oT1, sm_[2], NT);
        norm_relu_kernel<<<(unsigned)(((long)NS * 32 + 255) / 256), 256>>>(o1,  sm_[3], NS);

        // semantic attention for team (K=2); member/skill have K=1 -> identity
        cudaMemsetAsync(acc, 0, 128 * sizeof(float));
        sem_reduce_kernel<<<(NT + 63) / 64, 256>>>(oT0, kWp + (long)l * 4096, kbp + (long)l * 64, acc,      NT);
        sem_reduce_kernel<<<(NT + 63) / 64, 256>>>(oT1, kWp + (long)l * 4096, kbp + (long)l * 64, acc + 64, NT);
        sem_finalize_kernel<<<1, 64>>>(acc, qp + (long)l * 64, wsem);
        combine_kernel<<<(unsigned)(((long)NT * 16 + 255) / 256), 256>>>(x2, oT0, oT1, wsem);
    }

    // final shared linear, writing straight into d_out (member, skill, team order)
    proj_att_kernel<<<(NM + 63) / 64, 256>>>(o0, linW, linb, out, NM,
        nullptr, nullptr, nullptr, nullptr, nullptr, nullptr, nullptr, nullptr);
    proj_att_kernel<<<(NS + 63) / 64, 256>>>(o1, linW, linb, out + (long)NM * CC, NS,
        nullptr, nullptr, nullptr, nullptr, nullptr, nullptr, nullptr, nullptr);
    proj_att_kernel<<<(NT + 63) / 64, 256>>>(x2, linW, linb, out + (long)(NM + NS) * CC, NT,
        nullptr, nullptr, nullptr, nullptr, nullptr, nullptr, nullptr, nullptr);
}

// round 3
// speedup vs baseline: 1.4066x; 1.4066x over previous
#include <cuda_runtime.h>
#include <math.h>

// Problem constants
#define NM 100000
#define NS 20000
#define NT 200000
#define CC 64
#define EMT 1000000
#define EST 500000

// ---------------- static device scratch ----------------
__device__ float g_h0[NM * CC];    // projected member features
__device__ float g_h1[NS * CC];    // projected skill features
__device__ float g_h2[NT * CC];    // projected team features
__device__ float g_o0[NM * CC];    // member aggregation (edge type 1)
__device__ float g_o1[NS * CC];    // skill aggregation (edge type 3)
__device__ float g_oT0[NT * CC];   // team aggregation (edge type 0)
__device__ float g_oT1[NT * CC];   // team aggregation (edge type 2)
__device__ float g_as[4][NT * 2];  // per-edge-type source attention terms
__device__ float g_ad[4][NT * 2];  // per-edge-type dest attention terms
__device__ float g_sm[4][NT * 2];  // segment sum of exp
__device__ float g_acc[2 * CC];    // semantic attention accumulators (team, K=2)
__device__ float g_w[2];           // semantic softmax weights

// ---------------- fused projection + attention-dot kernel ----------------
// h = x @ W + b (per node row); x optionally blended: x = w[0]*xA + w[1]*xB.
// Plus up to 4 fused attention dot products:
//   ao[v][n*2+h] = sum_d h[n, h*32+d] * av[v][h*32+d]
__global__ __launch_bounds__(256) void proj_att_kernel(
    const float* __restrict__ xA, const float* __restrict__ xB,
    const float* __restrict__ wsem,
    const float* __restrict__ W, const float* __restrict__ bias,
    float* __restrict__ hout, int N,
    const float* av0, float* ao0, const float* av1, float* ao1,
    const float* av2, float* ao2, const float* av3, float* ao3)
{
    __shared__ float sWt[64 * 68];   // transposed weights: sWt[c*68 + k]
    __shared__ float sAv[4 * 64];
    __shared__ float sX[8][512];     // 8 warps x 8 rows x 64

    const float* avs[4] = {av0, av1, av2, av3};
    float*       aos[4] = {ao0, ao1, ao2, ao3};

    int t = threadIdx.x;
    for (int i = t; i < 4096; i += 256) { int k = i >> 6, c = i & 63; sWt[c * 68 + k] = W[i]; }
    if (t < 64) {
        #pragma unroll
        for (int v = 0; v < 4; v++) if (avs[v]) sAv[v * 64 + t] = avs[v][t];
    }
    __syncthreads();

    int lane = t & 31, slot = t >> 5;
    long r0 = (long)blockIdx.x * 64 + slot * 8;

    float w0 = 1.f, w1 = 0.f;
    if (xB) { w0 = wsem[0]; w1 = wsem[1]; }

    // load 8 rows of x into shared (zero padded), optional blend
    for (int j = lane; j < 128; j += 32) {
        int r = j >> 4, kk = (j & 15) * 4;
        float4 vv = make_float4(0.f, 0.f, 0.f, 0.f);
        if (r0 + r < N) {
            vv = *(const float4*)(xA + (r0 + r) * 64 + kk);
            if (xB) {
                float4 vb = *(const float4*)(xB + (r0 + r) * 64 + kk);
                vv.x = w0 * vv.x + w1 * vb.x;
                vv.y = w0 * vv.y + w1 * vb.y;
                vv.z = w0 * vv.z + w1 * vb.z;
                vv.w = w0 * vv.w + w1 * vb.w;
            }
        }
        *(float4*)&sX[slot][r * 64 + kk] = vv;
    }
    __syncwarp();

    float b0 = bias[lane], b1 = bias[lane + 32];
    float acc0[8], acc1[8];
    #pragma unroll
    for (int r = 0; r < 8; r++) { acc0[r] = b0; acc1[r] = b1; }

    #pragma unroll
    for (int k = 0; k < 64; k += 4) {
        float4 wv0 = *(const float4*)&sWt[lane * 68 + k];
        float4 wv1 = *(const float4*)&sWt[(lane + 32) * 68 + k];
        #pragma unroll
        for (int r = 0; r < 8; r++) {
            float4 xv = *(const float4*)&sX[slot][r * 64 + k];
            acc0[r] += xv.x * wv0.x + xv.y * wv0.y + xv.z * wv0.z + xv.w * wv0.w;
            acc1[r] += xv.x * wv1.x + xv.y * wv1.y + xv.z * wv1.z + xv.w * wv1.w;
        }
    }

    #pragma unroll
    for (int r = 0; r < 8; r++) {
        if (r0 + r < N) {
            hout[(r0 + r) * 64 + lane]      = acc0[r];
            hout[(r0 + r) * 64 + lane + 32] = acc1[r];
        }
    }

    // fused attention dots
    for (int v = 0; v < 4; v++) {
        if (!aos[v]) continue;
        float a0v = sAv[v * 64 + lane], a1v = sAv[v * 64 + lane + 32];
        #pragma unroll
        for (int r = 0; r < 8; r++) {
            float p0 = acc0[r] * a0v;
            float p1 = acc1[r] * a1v;
            #pragma unroll
            for (int off = 16; off; off >>= 1) {
                p0 += __shfl_xor_sync(0xffffffffu, p0, off);
                p1 += __shfl_xor_sync(0xffffffffu, p1, off);
            }
            if (lane == 0 && r0 + r < N) {
                aos[v][(r0 + r) * 2]     = p0;
                aos[v][(r0 + r) * 2 + 1] = p1;
            }
        }
    }
}

// ---------------- fused normalize+relu+semantic GEMM reduction ----------------
// o[n,c] = relu(o[n,c] / (sm[n,head(c)]+1e-16))  (written back)
// acc[c] += sum_n tanh((o_norm @ kW + kb)[n,c])
__global__ __launch_bounds__(256) void sem_norm_reduce_kernel(
    float* __restrict__ o, const float* __restrict__ sm,
    const float* __restrict__ W, const float* __restrict__ bias,
    float* __restrict__ acc, int N)
{
    __shared__ float sWt[64 * 68];
    __shared__ float sX[8][512];
    __shared__ float sAcc[64];

    int t = threadIdx.x;
    for (int i = t; i < 4096; i += 256) { int k = i >> 6, c = i & 63; sWt[c * 68 + k] = W[i]; }
    if (t < 64) sAcc[t] = 0.f;
    __syncthreads();

    int lane = t & 31, slot = t >> 5;
    long r0 = (long)blockIdx.x * 64 + slot * 8;

    for (int j = lane; j < 128; j += 32) {
        int r = j >> 4, kk = (j & 15) * 4;
        float4 vv = make_float4(0.f, 0.f, 0.f, 0.f);
        if (r0 + r < N) {
            long n = r0 + r;
            int head = kk >> 5;
            float inv = 1.0f / (sm[n * 2 + head] + 1e-16f);
            vv = *(const float4*)(o + n * 64 + kk);
            vv.x = fmaxf(vv.x * inv, 0.f);
            vv.y = fmaxf(vv.y * inv, 0.f);
            vv.z = fmaxf(vv.z * inv, 0.f);
            vv.w = fmaxf(vv.w * inv, 0.f);
            *(float4*)(o + n * 64 + kk) = vv;   // write normalized back
        }
        *(float4*)&sX[slot][r * 64 + kk] = vv;
    }
    __syncwarp();

    float b0 = bias[lane], b1 = bias[lane + 32];
    float acc0[8], acc1[8];
    #pragma unroll
    for (int r = 0; r < 8; r++) { acc0[r] = b0; acc1[r] = b1; }

    #pragma unroll
    for (int k = 0; k < 64; k += 4) {
        float4 w0 = *(const float4*)&sWt[lane * 68 + k];
        float4 w1 = *(const float4*)&sWt[(lane + 32) * 68 + k];
        #pragma unroll
        for (int r = 0; r < 8; r++) {
            float4 xv = *(const float4*)&sX[slot][r * 64 + k];
            acc0[r] += xv.x * w0.x + xv.y * w0.y + xv.z * w0.z + xv.w * w0.w;
            acc1[r] += xv.x * w1.x + xv.y * w1.y + xv.z * w1.z + xv.w * w1.w;
        }
    }

    float s0 = 0.f, s1 = 0.f;
    #pragma unroll
    for (int r = 0; r < 8; r++) {
        if (r0 + r < N) { s0 += tanhf(acc0[r]); s1 += tanhf(acc1[r]); }
    }
    atomicAdd(&sAcc[lane], s0);
    atomicAdd(&sAcc[lane + 32], s1);
    __syncthreads();
    if (t < 64) atomicAdd(&acc[t], sAcc[t]);
}

// ---------------- single-pass fused edge kernel ----------------
// Per edge (half-warp = 16 lanes per edge):
//   ex = exp(leaky_relu(as[src] + ad[dst]))   (no max subtraction; logits O(1))
//   sm[dst] += ex ; agg[dst] += ex * h[src]   (float4 vector atomics)
__global__ __launch_bounds__(256) void edge_fused_kernel(
    const int* __restrict__ src, const int* __restrict__ dst,
    const float* __restrict__ as, const float* __restrict__ ad,
    const float* __restrict__ hsrc,
    float* __restrict__ sm, float* __restrict__ agg, int E)
{
    long gt = (long)blockIdx.x * blockDim.x + threadIdx.x;
    long warp = gt >> 5;
    int lane = threadIdx.x & 31;
    int sub = lane >> 4, li = lane & 15;
    long e = warp * 2 + sub;
    if (e >= E) return;

    int s = src[e], d = dst[e];
    int head = li >> 3;   // columns li*4..li*4+3 all in head li>>3

    float logit = as[s * 2 + head] + ad[d * 2 + head];
    logit = (logit >= 0.f) ? logit : 0.2f * logit;   // leaky_relu 0.2
    float ex = __expf(logit);

    if (li == 0 || li == 8) atomicAdd(&sm[d * 2 + head], ex);

    float4 hv = *(const float4*)(hsrc + (long)s * 64 + li * 4);
    float4 v = make_float4(hv.x * ex, hv.y * ex, hv.z * ex, hv.w * ex);
    atomicAdd((float4*)(agg + (long)d * 64 + li * 4), v);
}

// agg[n,c] = relu(agg[n,c] / (sum[n, head(c)] + 1e-16))  (member/skill, no sem GEMM)
__global__ void norm_relu_kernel(float* __restrict__ agg, const float* __restrict__ sm, int N)
{
    long i = (long)blockIdx.x * blockDim.x + threadIdx.x;
    if (i >= (long)N * 16) return;
    int n = (int)(i >> 4), q = (int)(i & 15), head = q >> 3;
    float inv = 1.0f / (sm[n * 2 + head] + 1e-16f);
    float4 v = ((float4*)agg)[i];
    v.x = fmaxf(v.x * inv, 0.f);
    v.y = fmaxf(v.y * inv, 0.f);
    v.z = fmaxf(v.z * inv, 0.f);
    v.w = fmaxf(v.w * inv, 0.f);
    ((float4*)agg)[i] = v;
}

// ---------------- semantic finalize ----------------
__global__ void sem_finalize_kernel(const float* __restrict__ acc, const float* __restrict__ q,
                                    float* __restrict__ wout)
{
    __shared__ float s0[64], s1[64];
    int t = threadIdx.x;
    s0[t] = q[t] * acc[t]      * (1.0f / NT);
    s1[t] = q[t] * acc[64 + t] * (1.0f / NT);
    __syncthreads();
    if (t == 0) {
        float a = 0.f, b = 0.f;
        for (int i = 0; i < 64; i++) { a += s0[i]; b += s1[i]; }
        float m = fmaxf(a, b);
        float e0 = __expf(a - m), e1 = __expf(b - m);
        float inv = 1.0f / (e0 + e1);
        wout[0] = e0 * inv;
        wout[1] = e1 * inv;
    }
}

// ---------------- host orchestration ----------------
extern "C" void kernel_launch(void* const* d_in, const int* in_sizes, int n_in,
                              void* d_out, int out_size)
{
    (void)in_sizes; (void)n_in; (void)out_size;
    const float* x_m  = (const float*)d_in[0];
    const float* x_s  = (const float*)d_in[1];
    const float* x_t  = (const float*)d_in[2];
    const int* esrc[4] = {(const int*)d_in[3], (const int*)d_in[5], (const int*)d_in[7], (const int*)d_in[9]};
    const int* edst[4] = {(const int*)d_in[4], (const int*)d_in[6], (const int*)d_in[8], (const int*)d_in[10]};
    const float* Wp   = (const float*)d_in[11];
    const float* bp   = (const float*)d_in[12];
    const float* aS   = (const float*)d_in[13];
    const float* aD   = (const float*)d_in[14];
    const float* kWp  = (const float*)d_in[15];
    const float* kbp  = (const float*)d_in[16];
    const float* qp   = (const float*)d_in[17];
    const float* linW = (const float*)d_in[18];
    const float* linb = (const float*)d_in[19];
    float* out = (float*)d_out;

    float *h0, *h1, *h2, *o0, *o1, *oT0, *oT1, *acc, *wsem;
    float *asb, *adb, *smb;
    cudaGetSymbolAddress((void**)&h0,  g_h0);
    cudaGetSymbolAddress((void**)&h1,  g_h1);
    cudaGetSymbolAddress((void**)&h2,  g_h2);
    cudaGetSymbolAddress((void**)&o0,  g_o0);
    cudaGetSymbolAddress((void**)&o1,  g_o1);
    cudaGetSymbolAddress((void**)&oT0, g_oT0);
    cudaGetSymbolAddress((void**)&oT1, g_oT1);
    cudaGetSymbolAddress((void**)&acc, g_acc);
    cudaGetSymbolAddress((void**)&wsem, g_w);
    cudaGetSymbolAddress((void**)&asb, g_as);
    cudaGetSymbolAddress((void**)&adb, g_ad);
    cudaGetSymbolAddress((void**)&smb, g_sm);

    float* as_[4]; float* ad_[4]; float* sm_[4];
    for (int e = 0; e < 4; e++) {
        as_[e] = asb + (long)e * NT * 2;
        ad_[e] = adb + (long)e * NT * 2;
        sm_[e] = smb + (long)e * NT * 2;
    }

    const int EN[4] = {EMT, EMT, EST, EST};
    float* AGG[4] = {oT0, o0, oT1, o1};

    for (int l = 0; l < 3; l++) {
        const float* xm = l ? o0 : x_m;
        const float* xs = l ? o1 : x_s;
        // team input: blend of previous layer's oT0/oT1 with semantic weights
        const float* xtA = l ? oT0 : x_t;
        const float* xtB = l ? oT1 : nullptr;

        const float* W0 = Wp + (long)(l * 3 + 0) * 4096;
        const float* W1 = Wp + (long)(l * 3 + 1) * 4096;
        const float* W2 = Wp + (long)(l * 3 + 2) * 4096;
        const float* b0 = bp + (long)(l * 3 + 0) * 64;
        const float* b1 = bp + (long)(l * 3 + 1) * 64;
        const float* b2 = bp + (long)(l * 3 + 2) * 64;

        // projections with fused attention dot products (+ fused semantic blend for team)
        proj_att_kernel<<<(NM + 63) / 64, 256>>>(xm, nullptr, wsem, W0, b0, h0, NM,
            aS + (long)(l * 4 + 0) * 64, as_[0],
            aD + (long)(l * 4 + 1) * 64, ad_[1],
            nullptr, nullptr, nullptr, nullptr);
        proj_att_kernel<<<(NS + 63) / 64, 256>>>(xs, nullptr, wsem, W1, b1, h1, NS,
            aS + (long)(l * 4 + 2) * 64, as_[2],
            aD + (long)(l * 4 + 3) * 64, ad_[3],
            nullptr, nullptr, nullptr, nullptr);
        proj_att_kernel<<<(NT + 63) / 64, 256>>>(xtA, xtB, wsem, W2, b2, h2, NT,
            aS + (long)(l * 4 + 1) * 64, as_[1],
            aS + (long)(l * 4 + 3) * 64, as_[3],
            aD + (long)(l * 4 + 0) * 64, ad_[0],
            aD + (long)(l * 4 + 2) * 64, ad_[2]);

        // zero accumulators
        cudaMemsetAsync(smb, 0, (size_t)4 * NT * 2 * sizeof(float));
        cudaMemsetAsync(o0,  0, (size_t)NM * CC * sizeof(float));
        cudaMemsetAsync(o1,  0, (size_t)NS * CC * sizeof(float));
        cudaMemsetAsync(oT0, 0, (size_t)NT * CC * sizeof(float));
        cudaMemsetAsync(oT1, 0, (size_t)NT * CC * sizeof(float));

        const float* HS[4] = {h0, h2, h1, h2};
        for (int e = 0; e < 4; e++) {
            int E = EN[e];
            long warps = ((long)E + 1) / 2;
            long thr = warps * 32;
            edge_fused_kernel<<<(unsigned)((thr + 255) / 256), 256>>>(
                esrc[e], edst[e], as_[e], ad_[e], HS[e], sm_[e], AGG[e], E);
        }

        // member/skill: normalize only
        norm_relu_kernel<<<(unsigned)(((long)NM * 16 + 255) / 256), 256>>>(o0, sm_[1], NM);
        norm_relu_kernel<<<(unsigned)(((long)NS * 16 + 255) / 256), 256>>>(o1, sm_[3], NS);

        // team: fused normalize + semantic GEMM reduction (K=2)
        cudaMemsetAsync(acc, 0, 128 * sizeof(float));
        sem_norm_reduce_kernel<<<(NT + 63) / 64, 256>>>(oT0, sm_[0], kWp + (long)l * 4096, kbp + (long)l * 64, acc,      NT);
        sem_norm_reduce_kernel<<<(NT + 63) / 64, 256>>>(oT1, sm_[2], kWp + (long)l * 4096, kbp + (long)l * 64, acc + 64, NT);
        sem_finalize_kernel<<<1, 64>>>(acc, qp + (long)l * 64, wsem);
    }

    // final shared linear, writing straight into d_out (member, skill, team order)
    proj_att_kernel<<<(NM + 63) / 64, 256>>>(o0, nullptr, wsem, linW, linb, out, NM,
        nullptr, nullptr, nullptr, nullptr, nullptr, nullptr, nullptr, nullptr);
    proj_att_kernel<<<(NS + 63) / 64, 256>>>(o1, nullptr, wsem, linW, linb, out + (long)NM * CC, NS,
        nullptr, nullptr, nullptr, nullptr, nullptr, nullptr, nullptr, nullptr);
    proj_att_kernel<<<(NT + 63) / 64, 256>>>(oT0, oT1, wsem, linW, linb, out + (long)(NM + NS) * CC, NT,
        nullptr, nullptr, nullptr, nullptr, nullptr, nullptr, nullptr, nullptr);
}

// round 4
// speedup vs baseline: 1.4918x; 1.0606x over previous
#include <cuda_runtime.h>
#include <math.h>

// Problem constants
#define NM 100000
#define NS 20000
#define NT 200000
#define CC 64
#define EMT 1000000
#define EST 500000
#define MAXN NT

// ---------------- static device scratch ----------------
__device__ float g_h0[NM * CC];    // projected member features
__device__ float g_h1[NS * CC];    // projected skill features
__device__ float g_h2[NT * CC];    // projected team features
__device__ float g_o0[NM * CC];    // member aggregation (edge type 1)
__device__ float g_o1[NS * CC];    // skill aggregation (edge type 3)
__device__ float g_oT0[NT * CC];   // team aggregation (edge type 0)
__device__ float g_oT1[NT * CC];   // team aggregation (edge type 2)
__device__ float g_as[4][MAXN * 2];  // per-edge-type source attention terms
__device__ float g_ad[4][MAXN * 2];  // per-edge-type dest attention terms
__device__ float g_acc[2 * CC];    // semantic attention accumulators
__device__ float g_w[2];           // semantic softmax weights

// CSR scratch (built once per call, reused across 3 layers)
__device__ int g_cnt[4][MAXN + 1];
__device__ int g_off[4][MAXN + 1];
__device__ int g_fill[4][MAXN + 1];
__device__ int g_perm[2 * EMT + 2 * EST];
__device__ int g_bsum[4][128];

// ---------------- CSR build kernels ----------------
__global__ void hist_kernel(const int* __restrict__ dst, int* __restrict__ cnt, int E) {
    int i = blockIdx.x * blockDim.x + threadIdx.x;
    if (i < E) atomicAdd(&cnt[dst[i]], 1);
}

#define SCAN_BLOCK 1024
#define SCAN_ITEMS 2048

__global__ __launch_bounds__(SCAN_BLOCK) void scan1_kernel(
    const int* __restrict__ cnt, int* __restrict__ off, int* __restrict__ bsum, int n)
{
    __shared__ int wsum[32];
    int t = threadIdx.x;
    long base = (long)blockIdx.x * SCAN_ITEMS;
    long i0 = base + 2 * t, i1 = i0 + 1;
    int a0 = (i0 < n) ? cnt[i0] : 0;
    int a1 = (i1 < n) ? cnt[i1] : 0;
    int ts = a0 + a1;
    int lane = t & 31, w = t >> 5;
    int v = ts;
    #pragma unroll
    for (int o = 1; o < 32; o <<= 1) { int u = __shfl_up_sync(~0u, v, o); if (lane >= o) v += u; }
    if (lane == 31) wsum[w] = v;
    __syncthreads();
    if (w == 0) {
        int x = wsum[lane];
        #pragma unroll
        for (int o = 1; o < 32; o <<= 1) { int u = __shfl_up_sync(~0u, x, o); if (lane >= o) x += u; }
        wsum[lane] = x;   // inclusive warp-sum scan
    }
    __syncthreads();
    int warp_prefix = (w == 0) ? 0 : wsum[w - 1];
    int excl = warp_prefix + (v - ts);
    if (i0 < n) off[i0] = excl;
    if (i1 < n) off[i1] = excl + a0;
    if (t == 0) bsum[blockIdx.x] = wsum[31];
}

__global__ void scan2_kernel(int* __restrict__ bsum, int nb) {
    __shared__ int ws[4];
    int t = threadIdx.x;           // 128 threads
    int v = (t < nb) ? bsum[t] : 0;
    int lane = t & 31, w = t >> 5;
    int x = v;
    #pragma unroll
    for (int o = 1; o < 32; o <<= 1) { int u = __shfl_up_sync(~0u, x, o); if (lane >= o) x += u; }
    if (lane == 31) ws[w] = x;
    __syncthreads();
    if (t == 0) { int s = 0; for (int i = 0; i < 4; i++) { int c = ws[i]; ws[i] = s; s += c; } }
    __syncthreads();
    int excl = ws[w] + (x - v);
    if (t < nb) bsum[t] = excl;
}

__global__ void scan3_kernel(int* __restrict__ off, const int* __restrict__ bsum, int n) {
    long i = (long)blockIdx.x * blockDim.x + threadIdx.x;
    if (i < n) off[i] += bsum[i / SCAN_ITEMS];
}

__global__ void scatter_kernel(const int* __restrict__ dst, int* __restrict__ fill,
                               int* __restrict__ perm, int E) {
    int i = blockIdx.x * blockDim.x + threadIdx.x;
    if (i < E) {
        int pos = atomicAdd(&fill[dst[i]], 1);
        perm[pos] = i;
    }
}

// ---------------- fused projection + attention-dot kernel ----------------
__global__ __launch_bounds__(256) void proj_att_kernel(
    const float* __restrict__ xA, const float* __restrict__ xB,
    const float* __restrict__ wsem,
    const float* __restrict__ W, const float* __restrict__ bias,
    float* __restrict__ hout, int N,
    const float* av0, float* ao0, const float* av1, float* ao1,
    const float* av2, float* ao2, const float* av3, float* ao3)
{
    __shared__ float sWt[64 * 68];
    __shared__ float sAv[4 * 64];
    __shared__ float sX[8][512];

    const float* avs[4] = {av0, av1, av2, av3};
    float*       aos[4] = {ao0, ao1, ao2, ao3};

    int t = threadIdx.x;
    for (int i = t; i < 4096; i += 256) { int k = i >> 6, c = i & 63; sWt[c * 68 + k] = W[i]; }
    if (t < 64) {
        #pragma unroll
        for (int v = 0; v < 4; v++) if (avs[v]) sAv[v * 64 + t] = avs[v][t];
    }
    __syncthreads();

    int lane = t & 31, slot = t >> 5;
    long r0 = (long)blockIdx.x * 64 + slot * 8;

    float w0 = 1.f, w1 = 0.f;
    if (xB) { w0 = wsem[0]; w1 = wsem[1]; }

    for (int j = lane; j < 128; j += 32) {
        int r = j >> 4, kk = (j & 15) * 4;
        float4 vv = make_float4(0.f, 0.f, 0.f, 0.f);
        if (r0 + r < N) {
            vv = *(const float4*)(xA + (r0 + r) * 64 + kk);
            if (xB) {
                float4 vb = *(const float4*)(xB + (r0 + r) * 64 + kk);
                vv.x = w0 * vv.x + w1 * vb.x;
                vv.y = w0 * vv.y + w1 * vb.y;
                vv.z = w0 * vv.z + w1 * vb.z;
                vv.w = w0 * vv.w + w1 * vb.w;
            }
        }
        *(float4*)&sX[slot][r * 64 + kk] = vv;
    }
    __syncwarp();

    float b0 = bias[lane], b1 = bias[lane + 32];
    float acc0[8], acc1[8];
    #pragma unroll
    for (int r = 0; r < 8; r++) { acc0[r] = b0; acc1[r] = b1; }

    #pragma unroll
    for (int k = 0; k < 64; k += 4) {
        float4 wv0 = *(const float4*)&sWt[lane * 68 + k];
        float4 wv1 = *(const float4*)&sWt[(lane + 32) * 68 + k];
        #pragma unroll
        for (int r = 0; r < 8; r++) {
            float4 xv = *(const float4*)&sX[slot][r * 64 + k];
            acc0[r] += xv.x * wv0.x + xv.y * wv0.y + xv.z * wv0.z + xv.w * wv0.w;
            acc1[r] += xv.x * wv1.x + xv.y * wv1.y + xv.z * wv1.z + xv.w * wv1.w;
        }
    }

    #pragma unroll
    for (int r = 0; r < 8; r++) {
        if (r0 + r < N) {
            hout[(r0 + r) * 64 + lane]      = acc0[r];
            hout[(r0 + r) * 64 + lane + 32] = acc1[r];
        }
    }

    for (int v = 0; v < 4; v++) {
        if (!aos[v]) continue;
        float a0v = sAv[v * 64 + lane], a1v = sAv[v * 64 + lane + 32];
        #pragma unroll
        for (int r = 0; r < 8; r++) {
            float p0 = acc0[r] * a0v;
            float p1 = acc1[r] * a1v;
            #pragma unroll
            for (int off = 16; off; off >>= 1) {
                p0 += __shfl_xor_sync(0xffffffffu, p0, off);
                p1 += __shfl_xor_sync(0xffffffffu, p1, off);
            }
            if (lane == 0 && r0 + r < N) {
                aos[v][(r0 + r) * 2]     = p0;
                aos[v][(r0 + r) * 2 + 1] = p1;
            }
        }
    }
}

// ---------------- CSR gather-aggregate kernel ----------------
// Warp per destination node. Computes softmax-weighted aggregation in registers
// and writes relu(agg/sum) once. No atomics, no memset, no separate norm pass.
__global__ __launch_bounds__(256) void edge_gather_kernel(
    const int* __restrict__ perm, const int* __restrict__ off,
    const int* __restrict__ src, const float* __restrict__ as,
    const float* __restrict__ ad, const float* __restrict__ h,
    float* __restrict__ out, int N)
{
    int warp = (int)(((long)blockIdx.x * blockDim.x + threadIdx.x) >> 5);
    int lane = threadIdx.x & 31;
    if (warp >= N) return;
    int d = warp;
    int beg = off[d], end = off[d + 1];
    int head = lane >> 4;

    float2 adv = *(const float2*)(ad + (long)d * 2);
    float accx = 0.f, accy = 0.f, se0 = 0.f, se1 = 0.f;

    for (int base = beg; base < end; base += 32) {
        int idx = base + lane;
        bool valid = idx < end;
        int s = 0;
        float ex0 = 0.f, ex1 = 0.f;
        if (valid) {
            s = src[perm[idx]];
            float2 av = *(const float2*)(as + (long)s * 2);
            float l0 = av.x + adv.x; l0 = (l0 >= 0.f) ? l0 : 0.2f * l0;
            float l1 = av.y + adv.y; l1 = (l1 >= 0.f) ? l1 : 0.2f * l1;
            ex0 = __expf(l0); ex1 = __expf(l1);
            se0 += ex0; se1 += ex1;
        }
        int cnt = min(32, end - base);
        for (int i = 0; i < cnt; i++) {
            int si  = __shfl_sync(0xffffffffu, s, i);
            float e0 = __shfl_sync(0xffffffffu, ex0, i);
            float e1 = __shfl_sync(0xffffffffu, ex1, i);
            float exl = head ? e1 : e0;
            float2 hv = *(const float2*)(h + (long)si * 64 + lane * 2);
            accx += exl * hv.x;
            accy += exl * hv.y;
        }
    }

    #pragma unroll
    for (int o = 16; o; o >>= 1) {
        se0 += __shfl_xor_sync(0xffffffffu, se0, o);
        se1 += __shfl_xor_sync(0xffffffffu, se1, o);
    }
    float inv = 1.0f / ((head ? se1 : se0) + 1e-16f);
    accx = fmaxf(accx * inv, 0.f);
    accy = fmaxf(accy * inv, 0.f);
    *(float2*)(out + (long)d * 64 + lane * 2) = make_float2(accx, accy);
}

// ---------------- semantic GEMM reduction (read-only) ----------------
// acc[c] += sum_n tanh((o @ kW + kb)[n,c])
__global__ __launch_bounds__(256) void sem_reduce_kernel(
    const float* __restrict__ o, const float* __restrict__ W,
    const float* __restrict__ bias, float* __restrict__ acc, int N)
{
    __shared__ float sWt[64 * 68];
    __shared__ float sX[8][512];
    __shared__ float sAcc[64];

    int t = threadIdx.x;
    for (int i = t; i < 4096; i += 256) { int k = i >> 6, c = i & 63; sWt[c * 68 + k] = W[i]; }
    if (t < 64) sAcc[t] = 0.f;
    __syncthreads();

    int lane = t & 31, slot = t >> 5;
    long r0 = (long)blockIdx.x * 64 + slot * 8;

    for (int j = lane; j < 128; j += 32) {
        int r = j >> 4, kk = (j & 15) * 4;
        float4 vv = make_float4(0.f, 0.f, 0.f, 0.f);
        if (r0 + r < N) vv = *(const float4*)(o + (r0 + r) * 64 + kk);
        *(float4*)&sX[slot][r * 64 + kk] = vv;
    }
    __syncwarp();

    float b0 = bias[lane], b1 = bias[lane + 32];
    float acc0[8], acc1[8];
    #pragma unroll
    for (int r = 0; r < 8; r++) { acc0[r] = b0; acc1[r] = b1; }

    #pragma unroll
    for (int k = 0; k < 64; k += 4) {
        float4 w0 = *(const float4*)&sWt[lane * 68 + k];
        float4 w1 = *(const float4*)&sWt[(lane + 32) * 68 + k];
        #pragma unroll
        for (int r = 0; r < 8; r++) {
            float4 xv = *(const float4*)&sX[slot][r * 64 + k];
            acc0[r] += xv.x * w0.x + xv.y * w0.y + xv.z * w0.z + xv.w * w0.w;
            acc1[r] += xv.x * w1.x + xv.y * w1.y + xv.z * w1.z + xv.w * w1.w;
        }
    }

    float s0 = 0.f, s1 = 0.f;
    #pragma unroll
    for (int r = 0; r < 8; r++) {
        if (r0 + r < N) { s0 += tanhf(acc0[r]); s1 += tanhf(acc1[r]); }
    }
    atomicAdd(&sAcc[lane], s0);
    atomicAdd(&sAcc[lane + 32], s1);
    __syncthreads();
    if (t < 64) atomicAdd(&acc[t], sAcc[t]);
}

// ---------------- semantic finalize ----------------
__global__ void sem_finalize_kernel(const float* __restrict__ acc, const float* __restrict__ q,
                                    float* __restrict__ wout)
{
    __shared__ float s0[64], s1[64];
    int t = threadIdx.x;
    s0[t] = q[t] * acc[t]      * (1.0f / NT);
    s1[t] = q[t] * acc[64 + t] * (1.0f / NT);
    __syncthreads();
    if (t == 0) {
        float a = 0.f, b = 0.f;
        for (int i = 0; i < 64; i++) { a += s0[i]; b += s1[i]; }
        float m = fmaxf(a, b);
        float e0 = __expf(a - m), e1 = __expf(b - m);
        float inv = 1.0f / (e0 + e1);
        wout[0] = e0 * inv;
        wout[1] = e1 * inv;
    }
}

// ---------------- host orchestration ----------------
extern "C" void kernel_launch(void* const* d_in, const int* in_sizes, int n_in,
                              void* d_out, int out_size)
{
    (void)in_sizes; (void)n_in; (void)out_size;
    const float* x_m  = (const float*)d_in[0];
    const float* x_s  = (const float*)d_in[1];
    const float* x_t  = (const float*)d_in[2];
    const int* esrc[4] = {(const int*)d_in[3], (const int*)d_in[5], (const int*)d_in[7], (const int*)d_in[9]};
    const int* edst[4] = {(const int*)d_in[4], (const int*)d_in[6], (const int*)d_in[8], (const int*)d_in[10]};
    const float* Wp   = (const float*)d_in[11];
    const float* bp   = (const float*)d_in[12];
    const float* aS   = (const float*)d_in[13];
    const float* aD   = (const float*)d_in[14];
    const float* kWp  = (const float*)d_in[15];
    const float* kbp  = (const float*)d_in[16];
    const float* qp   = (const float*)d_in[17];
    const float* linW = (const float*)d_in[18];
    const float* linb = (const float*)d_in[19];
    float* out = (float*)d_out;

    float *h0, *h1, *h2, *o0, *o1, *oT0, *oT1, *acc, *wsem, *asb, *adb;
    int *cntb, *offb, *fillb, *permb, *bsumb;
    cudaGetSymbolAddress((void**)&h0,  g_h0);
    cudaGetSymbolAddress((void**)&h1,  g_h1);
    cudaGetSymbolAddress((void**)&h2,  g_h2);
    cudaGetSymbolAddress((void**)&o0,  g_o0);
    cudaGetSymbolAddress((void**)&o1,  g_o1);
    cudaGetSymbolAddress((void**)&oT0, g_oT0);
    cudaGetSymbolAddress((void**)&oT1, g_oT1);
    cudaGetSymbolAddress((void**)&acc, g_acc);
    cudaGetSymbolAddress((void**)&wsem, g_w);
    cudaGetSymbolAddress((void**)&asb, g_as);
    cudaGetSymbolAddress((void**)&adb, g_ad);
    cudaGetSymbolAddress((void**)&cntb, g_cnt);
    cudaGetSymbolAddress((void**)&offb, g_off);
    cudaGetSymbolAddress((void**)&fillb, g_fill);
    cudaGetSymbolAddress((void**)&permb, g_perm);
    cudaGetSymbolAddress((void**)&bsumb, g_bsum);

    float* as_[4]; float* ad_[4];
    int* cnt_[4]; int* off_[4]; int* fill_[4]; int* perm_[4]; int* bsum_[4];
    const long permoff[4] = {0, EMT, 2L * EMT, 2L * EMT + EST};
    for (int e = 0; e < 4; e++) {
        as_[e]  = asb + (long)e * MAXN * 2;
        ad_[e]  = adb + (long)e * MAXN * 2;
        cnt_[e]  = cntb  + (long)e * (MAXN + 1);
        off_[e]  = offb  + (long)e * (MAXN + 1);
        fill_[e] = fillb + (long)e * (MAXN + 1);
        bsum_[e] = bsumb + (long)e * 128;
        perm_[e] = permb + permoff[e];
    }

    const int EN[4] = {EMT, EMT, EST, EST};
    const int ND[4] = {NT, NM, NT, NS};   // destination node counts
    float* AGG[4] = {oT0, o0, oT1, o1};

    // ---- build CSR once (reused across all 3 layers) ----
    for (int e = 0; e < 4; e++) {
        int n = ND[e], E = EN[e];
        int nscan = n + 1;
        int nb = (nscan + SCAN_ITEMS - 1) / SCAN_ITEMS;
        cudaMemsetAsync(cnt_[e], 0, (size_t)nscan * sizeof(int));
        hist_kernel<<<(E + 255) / 256, 256>>>(edst[e], cnt_[e], E);
        scan1_kernel<<<nb, SCAN_BLOCK>>>(cnt_[e], off_[e], bsum_[e], nscan);
        scan2_kernel<<<1, 128>>>(bsum_[e], nb);
        scan3_kernel<<<(nscan + 255) / 256, 256>>>(off_[e], bsum_[e], nscan);
        cudaMemcpyAsync(fill_[e], off_[e], (size_t)nscan * sizeof(int),
                        cudaMemcpyDeviceToDevice);
        scatter_kernel<<<(E + 255) / 256, 256>>>(edst[e], fill_[e], perm_[e], E);
    }

    for (int l = 0; l < 3; l++) {
        const float* xm = l ? o0 : x_m;
        const float* xs = l ? o1 : x_s;
        const float* xtA = l ? oT0 : x_t;
        const float* xtB = l ? oT1 : nullptr;

        const float* W0 = Wp + (long)(l * 3 + 0) * 4096;
        const float* W1 = Wp + (long)(l * 3 + 1) * 4096;
        const float* W2 = Wp + (long)(l * 3 + 2) * 4096;
        const float* b0 = bp + (long)(l * 3 + 0) * 64;
        const float* b1 = bp + (long)(l * 3 + 1) * 64;
        const float* b2 = bp + (long)(l * 3 + 2) * 64;

        proj_att_kernel<<<(NM + 63) / 64, 256>>>(xm, nullptr, wsem, W0, b0, h0, NM,
            aS + (long)(l * 4 + 0) * 64, as_[0],
            aD + (long)(l * 4 + 1) * 64, ad_[1],
            nullptr, nullptr, nullptr, nullptr);
        proj_att_kernel<<<(NS + 63) / 64, 256>>>(xs, nullptr, wsem, W1, b1, h1, NS,
            aS + (long)(l * 4 + 2) * 64, as_[2],
            aD + (long)(l * 4 + 3) * 64, ad_[3],
            nullptr, nullptr, nullptr, nullptr);
        proj_att_kernel<<<(NT + 63) / 64, 256>>>(xtA, xtB, wsem, W2, b2, h2, NT,
            aS + (long)(l * 4 + 1) * 64, as_[1],
            aS + (long)(l * 4 + 3) * 64, as_[3],
            aD + (long)(l * 4 + 0) * 64, ad_[0],
            aD + (long)(l * 4 + 2) * 64, ad_[2]);

        const float* HS[4] = {h0, h2, h1, h2};
        for (int e = 0; e < 4; e++) {
            int n = ND[e];
            long thr = (long)n * 32;
            edge_gather_kernel<<<(unsigned)((thr + 255) / 256), 256>>>(
                perm_[e], off_[e], esrc[e], as_[e], ad_[e], HS[e], AGG[e], n);
        }

        // team semantic attention (K=2); member/skill K=1 -> identity
        cudaMemsetAsync(acc, 0, 128 * sizeof(float));
        sem_reduce_kernel<<<(NT + 63) / 64, 256>>>(oT0, kWp + (long)l * 4096, kbp + (long)l * 64, acc,      NT);
        sem_reduce_kernel<<<(NT + 63) / 64, 256>>>(oT1, kWp + (long)l * 4096, kbp + (long)l * 64, acc + 64, NT);
        sem_finalize_kernel<<<1, 64>>>(acc, qp + (long)l * 64, wsem);
    }

    // final shared linear, writing straight into d_out (member, skill, team order)
    proj_att_kernel<<<(NM + 63) / 64, 256>>>(o0, nullptr, wsem, linW, linb, out, NM,
        nullptr, nullptr, nullptr, nullptr, nullptr, nullptr, nullptr, nullptr);
    proj_att_kernel<<<(NS + 63) / 64, 256>>>(o1, nullptr, wsem, linW, linb, out + (long)NM * CC, NS,
        nullptr, nullptr, nullptr, nullptr, nullptr, nullptr, nullptr, nullptr);
    proj_att_kernel<<<(NT + 63) / 64, 256>>>(oT0, oT1, wsem, linW, linb, out + (long)(NM + NS) * CC, NT,
        nullptr, nullptr, nullptr, nullptr, nullptr, nullptr, nullptr, nullptr);
}